// round 10
// baseline (speedup 1.0000x reference)
#include <cuda_runtime.h>
#include <cuda_bf16.h>

#define OUT_W    256
#define IMG_W    512
#define NBLK     512            // (ii in 256) x (i-half h in 2)
#define SK_T     16             // K rows per block
#define SK_W     388            // bf16x2 words per K row; 1552B = 16 mod 128
#define SREV_LEN 1032
#define OFF_K     0
#define OFF_SREV  24832         // 16*388*4
#define OFF_SREVB 26896
#define SMEM_BYTES 28960

#define NCHUNK   512            // (ii) x (e-half se)

__device__ float g_part[NCHUNK * 32 * OUT_W];   // 16 MB partials [chunk][i][j]

__device__ __forceinline__ float frcp(float x) {
    float r; asm("rcp.approx.f32 %0, %1;" : "=f"(r) : "f"(x)); return r;
}
__device__ __forceinline__ void mma_bf16(float* d, unsigned a0, unsigned a1,
                                         unsigned a2, unsigned a3,
                                         unsigned b0, unsigned b1) {
    asm volatile(
        "mma.sync.aligned.m16n8k16.row.col.f32.bf16.bf16.f32 "
        "{%0,%1,%2,%3}, {%4,%5,%6,%7}, {%8,%9}, {%0,%1,%2,%3};"
        : "+f"(d[0]), "+f"(d[1]), "+f"(d[2]), "+f"(d[3])
        : "r"(a0), "r"(a1), "r"(a2), "r"(a3), "r"(b0), "r"(b1));
}

// ---------------------------------------------------------------------------
// Block (ii, h): one image row ii, i in [16h, 16h+16). 8 warps =
// (wj in 0..3: j-strip [64wj, 64wj+64), 4 m-tiles) x (se in 0..1: e-half).
// Warp: 18 k-steps, 8 MMAs/step sharing one 9-word Toeplitz A window
// (a3==a0, cross-m word reuse) + 4 B words -> 13 LDS per 8 MMAs.
// 512 blocks, launch_bounds(256,4) -> 4 blocks/SM, single wave.
// ---------------------------------------------------------------------------
__global__ void __launch_bounds__(256, 4)
conv_mma_kernel(const float* __restrict__ img, const float* __restrict__ pos) {
    extern __shared__ char smem[];
    unsigned*      skw = (unsigned*)(smem + OFF_K);
    __nv_bfloat16* sr  = (__nv_bfloat16*)(smem + OFF_SREV);   // reversed row
    __nv_bfloat16* srB = (__nv_bfloat16*)(smem + OFF_SREVB);  // shifted +1

    const int ii  = blockIdx.x >> 1;
    const int h   = blockIdx.x & 1;
    const int tid = threadIdx.x;
    const float p0 = pos[0], p1 = pos[1];

    // ---- stage reversed image row (bf16): sr[z] = img[ii][767-z], z in [256,767]
    for (int z = tid; z < SREV_LEN; z += 256) {
        float v0 = (z >= 256 && z <= 767) ? img[ii * IMG_W + (767 - z)] : 0.f;
        int z1 = z + 1;
        float v1 = (z1 >= 256 && z1 <= 767) ? img[ii * IMG_W + (767 - z1)] : 0.f;
        sr [z] = __float2bfloat16_rn(v0);
        srB[z] = __float2bfloat16_rn(v1);
    }
    // ---- K rows: row t serves i = 16h + t  (d-255 = 16h + t - ii)
    for (int t = 0; t < SK_T; t++) {
        float dx  = (float)(16 * h + t - ii) + p0;
        float dx2 = dx * dx;
        for (int u = tid; u < SK_W; u += 256) {
            float dy0 = (float)(2 * u - 511) + p1;
            float dy1 = dy0 + 1.0f;
            float v0 = (2 * u     < 767) ? frcp(fmaf(dy0, dy0, dx2)) : 0.f;
            float v1 = (2 * u + 1 < 767) ? frcp(fmaf(dy1, dy1, dx2)) : 0.f;
            unsigned wv;
            asm("cvt.rn.bf16x2.f32 %0, %1, %2;" : "=r"(wv) : "f"(v1), "f"(v0));
            skw[t * SK_W + u] = wv;
        }
    }
    __syncthreads();

    const int w    = tid >> 5;
    const int wj   = w & 3;           // j strip [64wj, 64wj+64)
    const int se   = w >> 2;          // e-half
    const int lane = tid & 31;
    const int r    = lane >> 2;
    const int c    = lane & 3;
    const int sel  = r & 1;

    const unsigned* As = (const unsigned*)(sel ? srB : sr);
    const int aw0 = (2 * c - 64 * wj - r + 256 - sel) >> 1;
    const unsigned* pB = skw + r * SK_W + c;

    float acc[4][2][4];
#pragma unroll
    for (int m = 0; m < 4; m++)
#pragma unroll
        for (int n = 0; n < 2; n++)
#pragma unroll
            for (int k = 0; k < 4; k++) acc[m][n][k] = 0.f;

    // k-steps q in [18se, 18se+18): e-words [32wj+8q, +8)
#pragma unroll 1
    for (int q = 18 * se; q < 18 * se + 18; q++) {
        const int ew = 32 * wj + 8 * q;
        const int w0 = aw0 + ew;
        unsigned W[9];
#pragma unroll
        for (int k = 0; k < 9; k++) W[k] = As[w0 + 4 - 4 * k];
        unsigned b00 = pB[ew],            b01 = pB[ew + 4];
        unsigned b10 = pB[8 * SK_W + ew], b11 = pB[8 * SK_W + ew + 4];
#pragma unroll
        for (int m = 0; m < 4; m++) {
            mma_bf16(acc[m][0], W[2*m+1], W[2*m+2], W[2*m], W[2*m+1], b00, b01);
            mma_bf16(acc[m][1], W[2*m+1], W[2*m+2], W[2*m], W[2*m+1], b10, b11);
        }
    }

    // ---- partials: chunk (ii, se); rows i = 16h + (8nn + 2c), cols j
    float* dst = g_part + (ii * 2 + se) * (32 * OUT_W) + (16 * h) * OUT_W;
#pragma unroll
    for (int m = 0; m < 4; m++) {
        const int j0 = 64 * wj + 16 * m + r;
#pragma unroll
        for (int nn = 0; nn < 2; nn++) {
            const int il = 8 * nn + 2 * c;
            dst[(il    ) * OUT_W + j0    ] = acc[m][nn][0];
            dst[(il + 1) * OUT_W + j0    ] = acc[m][nn][1];
            dst[(il    ) * OUT_W + j0 + 8] = acc[m][nn][2];
            dst[(il + 1) * OUT_W + j0 + 8] = acc[m][nn][3];
        }
    }
}

// ---------------------------------------------------------------------------
// Fused single-kernel reduction over 512 chunks (deterministic).
// 16 threads cooperate per float4 output: each sums 32 chunks, then one
// thread folds the 16 partials in fixed order.
// ---------------------------------------------------------------------------
__global__ void reduce_kernel(float* __restrict__ out) {
    __shared__ float4 sred[256];
    const int t  = threadIdx.x;
    const int oi = t >> 4;                       // 16 outputs per block
    const int tt = t & 15;                       // 16 workers per output
    const int o4 = blockIdx.x * 16 + oi;         // float4 index in [0, 2048)
    const float4* src = (const float4*)g_part;

    float4 s = make_float4(0.f, 0.f, 0.f, 0.f);
#pragma unroll 8
    for (int cidx = 0; cidx < 32; cidx++) {
        float4 v = src[(32 * tt + cidx) * 2048 + o4];
        s.x += v.x; s.y += v.y; s.z += v.z; s.w += v.w;
    }
    sred[t] = s;
    __syncthreads();
    if (tt == 0) {
        float4 a = sred[oi * 16];
#pragma unroll
        for (int k = 1; k < 16; k++) {
            float4 v = sred[oi * 16 + k];
            a.x += v.x; a.y += v.y; a.z += v.z; a.w += v.w;
        }
        ((float4*)out)[o4] = a;
    }
}

// ---------------------------------------------------------------------------
extern "C" void kernel_launch(void* const* d_in, const int* in_sizes, int n_in,
                              void* d_out, int out_size) {
    const float* img = (const float*)d_in[0];   // [256, 512] f32
    const float* pos = (const float*)d_in[1];   // [2] f32
    float* out = (float*)d_out;                 // [32, 256] f32

    conv_mma_kernel<<<NBLK, 256, SMEM_BYTES>>>(img, pos);
    reduce_kernel<<<128, 256>>>(out);
}